// round 8
// baseline (speedup 1.0000x reference)
#include <cuda_runtime.h>
#include <math.h>

#define NB 128
#define NT 30
#define NG 13
#define NC 16
#define NCELLS 169
#define NROWS 507            // 169*3 anchor rows used per batch
#define ROWLEN 21
#define ROWS_FULL 10647
#define PSTRIDE 22           // padded row stride in smem

__device__ float    g_acc   = 0.0f;
__device__ unsigned g_count = 0u;

__device__ __forceinline__ void red_release_add_f32(float* addr, float v) {
    asm volatile("red.release.gpu.add.f32 [%0], %1;" :: "l"(addr), "f"(v) : "memory");
}
__device__ __forceinline__ void red_release_add_u32(unsigned* addr, unsigned v) {
    asm volatile("red.release.gpu.add.u32 [%0], %1;" :: "l"(addr), "r"(v) : "memory");
}
__device__ __forceinline__ unsigned ld_acquire_u32(const unsigned* addr) {
    unsigned v;
    asm volatile("ld.acquire.gpu.u32 %0, [%1];" : "=r"(v) : "l"(addr) : "memory");
    return v;
}
__device__ __forceinline__ float ld_relaxed_f32(const float* addr) {
    float v;
    asm volatile("ld.relaxed.gpu.f32 %0, [%1];" : "=f"(v) : "l"(addr) : "memory");
    return v;
}

__device__ __forceinline__ float warp_sum(float v) {
    #pragma unroll
    for (int o = 16; o > 0; o >>= 1) v += __shfl_down_sync(0xffffffffu, v, o);
    return v;
}

__global__ void __launch_bounds__(512) region_loss_kernel(
    const float* __restrict__ outp,   // (128, 10647, 21)
    const float* __restrict__ tgt,    // (128, 30, 5)
    float* __restrict__ loss)
{
    const int b   = blockIdx.x;
    const int tid = threadIdx.x;
    const size_t base = (size_t)b * ((size_t)ROWS_FULL * ROWLEN);

    __shared__ int   s_cell2t[NCELLS];
    __shared__ float s_ti[NT][5];        // x1,y1,x2,y2,cls per target
    __shared__ int   s_idx[NT];
    __shared__ float s_p[90 * PSTRIDE];  // staged target-cell rows
    __shared__ float s_warp[16];

    // ---- phase 0: independent global loads issued immediately ----
    float conf = 0.0f;
    if (tid < NROWS) conf = __ldg(outp + base + (size_t)tid * ROWLEN + 4);

    float tx1 = 0, ty1 = 0, tx2 = 0, ty2 = 0, tcl = 0;
    if (tid < NT) {
        const float* tg = tgt + ((size_t)b * NT + tid) * 5;
        tx1 = __ldg(tg + 0); ty1 = __ldg(tg + 1);
        tx2 = __ldg(tg + 2); ty2 = __ldg(tg + 3);
        tcl = __ldg(tg + 4);
    }
    if (tid < NCELLS) s_cell2t[tid] = -1;
    __syncthreads();   // orders cell2t init vs scatter below

    // ---- phase 1a: scatter cell map + target info (30 threads) ----
    if (tid < NT) {
        const float lx = (tx1 + tx2) * 0.5f;
        const float ly = (ty1 + ty2) * 0.5f;
        const int idx = (int)floorf(ly / 32.0f) * NG + (int)floorf(lx / 32.0f);
        s_ti[tid][0] = tx1; s_ti[tid][1] = ty1;
        s_ti[tid][2] = tx2; s_ti[tid][3] = ty2;
        s_ti[tid][4] = tcl;
        s_idx[tid]   = idx;
        s_cell2t[idx] = tid;
    }
    __syncthreads();

    // ---- phase 1b: staged row gather (21 consecutive threads per row) ----
    {
        const int r0  = tid / ROWLEN;        // 0..24 (tid<504)
        const int col = tid - r0 * ROWLEN;   // 0..20
        #pragma unroll
        for (int it = 0; it < 4; it++) {
            const int row = it * 24 + r0;
            if (tid < 504 && row < 90) {
                const int t = row / 3;
                const int a = row - t * 3;
                s_p[row * PSTRIDE + col] =
                    __ldg(outp + base + ((size_t)s_idx[t] * 3 + a) * ROWLEN + col);
            }
        }
    }
    __syncthreads();

    // ---- phase 2: per-row loss ----
    const float SQRT5 = 2.2360679774997896f;
    const float INVW  = 1.0f / 416.0f;
    float acc = 0.0f;
    if (tid < NROWS) {
        const int cell = tid / 3;
        const int a    = tid - cell * 3;
        const int t    = s_cell2t[cell];
        if (t < 0) {
            acc = conf * conf;
        } else {
            const float x1 = s_ti[t][0], y1 = s_ti[t][1];
            const float x2 = s_ti[t][2], y2 = s_ti[t][3];
            const float a2 = (x2 - x1) * (y2 - y1);
            float iou[3];
            #pragma unroll
            for (int aa = 0; aa < 3; aa++) {
                const float* p = s_p + (t * 3 + aa) * PSTRIDE;
                const float px = p[0], py = p[1], pw = p[2], ph = p[3];
                const float bx1 = px - pw * 0.5f, by1 = py - ph * 0.5f;
                const float bx2 = px + pw * 0.5f, by2 = py + ph * 0.5f;
                const float ix1 = fmaxf(bx1, x1), iy1 = fmaxf(by1, y1);
                const float ix2 = fminf(bx2, x2), iy2 = fminf(by2, y2);
                const float inter = fmaxf(ix2 - ix1, 0.0f) * fmaxf(iy2 - iy1, 0.0f);
                const float a1 = (bx2 - bx1) * (by2 - by1);
                iou[aa] = inter / (a1 + a2 - inter + 1e-16f);
            }
            float best = iou[0]; int best_a = 0;
            if (iou[1] > best) { best = iou[1]; best_a = 1; }
            if (iou[2] > best) { best = iou[2]; best_a = 2; }

            if (a == best_a) {
                const float d = (conf - best) * SQRT5;
                acc = d * d;
                const float* p = s_p + (t * 3 + a) * PSTRIDE;
                const float lx = (x1 + x2) * 0.5f;
                const float ly = (y1 + y2) * 0.5f;
                const float tw = x2 - x1, th = y2 - y1;
                const float k  = (2.0f - (tw * INVW) * (th * INVW)) * INVW;
                const float dx = (p[0] - lx) * k;
                const float dy = (p[1] - ly) * k;
                const float dw = (p[2] - tw) * k;
                const float dh = (p[3] - th) * k;
                acc += dx*dx + dy*dy + dw*dw + dh*dh;
                const int c0 = (int)s_ti[t][4];
                #pragma unroll
                for (int c = 0; c < NC; c++) {
                    const float d2 = p[5 + c] - (c == c0 ? 1.0f : 0.0f);
                    acc += d2 * d2;
                }
            } else {
                const float cm = (iou[a] > 0.5f) ? 0.0f : 1.0f;
                const float d  = conf * cm;
                acc = d * d;
            }
        }
    }
    acc *= 0.5f;

    // ---- block reduce ----
    acc = warp_sum(acc);
    const int lane = tid & 31, wid = tid >> 5;
    if (lane == 0) s_warp[wid] = acc;
    __syncthreads();
    if (wid == 0) {
        float x = (lane < 16) ? s_warp[lane] : 0.0f;
        x = warp_sum(x);
        if (lane == 0) {
            // workers: release-ordered fire-and-forget REDs; NO fence, NO drain wait
            red_release_add_f32(&g_acc, x);
            red_release_add_u32(&g_count, 1u);

            if (b == 0) {
                // only block 0 waits; acquire pairs with workers' releases
                while (ld_acquire_u32(&g_count) < (unsigned)NB) {}
                const float total = ld_relaxed_f32(&g_acc);  // stable now
                loss[0] = total;                              // publish
                g_acc   = 0.0f;                               // reset for next replay
                g_count = 0u;   // visible to next launch via kernel boundary
            }
        }
    }
}

extern "C" void kernel_launch(void* const* d_in, const int* in_sizes, int n_in,
                              void* d_out, int out_size) {
    const float* outp = (const float*)d_in[0];
    const float* tgt  = (const float*)d_in[1];
    float* loss = (float*)d_out;
    region_loss_kernel<<<NB, 512>>>(outp, tgt, loss);
}

// round 9
// speedup vs baseline: 1.3217x; 1.3217x over previous
#include <cuda_runtime.h>
#include <math.h>

#define NB 128
#define NT 30
#define NG 13
#define NC 16
#define NCELLS 169
#define NROWS 507            // 169*3 anchor rows used per batch
#define ROWLEN 21
#define ROWS_FULL 10647
#define PSTRIDE 22           // padded row stride in smem
#define GELEMS (90 * ROWLEN) // 1890 staged elements

__device__ __forceinline__ float warp_sum(float v) {
    #pragma unroll
    for (int o = 16; o > 0; o >>= 1) v += __shfl_down_sync(0xffffffffu, v, o);
    return v;
}

__global__ void __launch_bounds__(512) region_loss_kernel(
    const float* __restrict__ outp,   // (128, 10647, 21)
    const float* __restrict__ tgt,    // (128, 30, 5)
    float* __restrict__ loss)
{
    const int b   = blockIdx.x;
    const int tid = threadIdx.x;
    const size_t base = (size_t)b * ((size_t)ROWS_FULL * ROWLEN);
    const float* tb = tgt + (size_t)b * (NT * 5);

    __shared__ float s_ti[NT][5];        // x1,y1,x2,y2,cls
    __shared__ int   s_idx[NT];
    __shared__ float s_p[90 * PSTRIDE];  // staged target-cell rows
    __shared__ float s_warp[16];

    // ================= phase 0: everything before ONE sync =================

    // conf loads (independent)
    float conf = 0.0f;
    if (tid < NROWS) conf = __ldg(outp + base + (size_t)tid * ROWLEN + 4);

    // target table writers (30 threads) — independent of gather path
    if (tid < NT) {
        const float* tg = tb + tid * 5;
        const float x1 = __ldg(tg + 0), y1 = __ldg(tg + 1);
        const float x2 = __ldg(tg + 2), y2 = __ldg(tg + 3);
        const float cl = __ldg(tg + 4);
        s_ti[tid][0] = x1; s_ti[tid][1] = y1;
        s_ti[tid][2] = x2; s_ti[tid][3] = y2;
        s_ti[tid][4] = cl;
        const float lx = (x1 + x2) * 0.5f;
        const float ly = (y1 + y2) * 0.5f;
        s_idx[tid] = (int)floorf(ly / 32.0f) * NG + (int)floorf(lx / 32.0f);
    }

    // staged gather: each thread resolves its own rows (tgt LDG -> idx -> gather LDG),
    // no barrier needed before the gather.
    if (tid < 504) {
        #pragma unroll
        for (int it = 0; it < 4; it++) {
            const int e = tid + it * 504;
            if (e < GELEMS) {
                const int row = e / ROWLEN;
                const int col = e - row * ROWLEN;
                const int t   = row / 3;
                const int a   = row - t * 3;
                const float* tg = tb + t * 5;
                const float x1 = __ldg(tg + 0), y1 = __ldg(tg + 1);
                const float x2 = __ldg(tg + 2), y2 = __ldg(tg + 3);
                const float lx = (x1 + x2) * 0.5f;
                const float ly = (y1 + y2) * 0.5f;
                const int idx = (int)floorf(ly / 32.0f) * NG + (int)floorf(lx / 32.0f);
                s_p[row * PSTRIDE + col] =
                    __ldg(outp + base + ((size_t)idx * 3 + a) * ROWLEN + col);
            }
        }
    }

    __syncthreads();   // the ONLY barrier: s_ti, s_idx, s_p all visible

    // ================= phase 1: per-row loss =================
    const float SQRT5 = 2.2360679774997896f;
    const float INVW  = 1.0f / 416.0f;
    float acc = 0.0f;
    if (tid < NROWS) {
        const int cell = tid / 3;
        const int a    = tid - cell * 3;

        // find target owning this cell (cells are distinct; -1 if none)
        int t = -1;
        #pragma unroll
        for (int k = 0; k < NT; k++)
            if (s_idx[k] == cell) t = k;

        if (t < 0) {
            acc = conf * conf;
        } else {
            const float x1 = s_ti[t][0], y1 = s_ti[t][1];
            const float x2 = s_ti[t][2], y2 = s_ti[t][3];
            const float a2 = (x2 - x1) * (y2 - y1);
            float iou[3];
            #pragma unroll
            for (int aa = 0; aa < 3; aa++) {
                const float* p = s_p + (t * 3 + aa) * PSTRIDE;
                const float px = p[0], py = p[1], pw = p[2], ph = p[3];
                const float bx1 = px - pw * 0.5f, by1 = py - ph * 0.5f;
                const float bx2 = px + pw * 0.5f, by2 = py + ph * 0.5f;
                const float ix1 = fmaxf(bx1, x1), iy1 = fmaxf(by1, y1);
                const float ix2 = fminf(bx2, x2), iy2 = fminf(by2, y2);
                const float inter = fmaxf(ix2 - ix1, 0.0f) * fmaxf(iy2 - iy1, 0.0f);
                const float a1 = (bx2 - bx1) * (by2 - by1);
                iou[aa] = inter / (a1 + a2 - inter + 1e-16f);
            }
            float best = iou[0]; int best_a = 0;
            if (iou[1] > best) { best = iou[1]; best_a = 1; }
            if (iou[2] > best) { best = iou[2]; best_a = 2; }

            if (a == best_a) {
                const float d = (conf - best) * SQRT5;
                acc = d * d;
                const float* p = s_p + (t * 3 + a) * PSTRIDE;
                const float lx = (x1 + x2) * 0.5f;
                const float ly = (y1 + y2) * 0.5f;
                const float tw = x2 - x1, th = y2 - y1;
                const float k  = (2.0f - (tw * INVW) * (th * INVW)) * INVW;
                const float dx = (p[0] - lx) * k;
                const float dy = (p[1] - ly) * k;
                const float dw = (p[2] - tw) * k;
                const float dh = (p[3] - th) * k;
                acc += dx*dx + dy*dy + dw*dw + dh*dh;
                const int c0 = (int)s_ti[t][4];
                #pragma unroll
                for (int c = 0; c < NC; c++) {
                    const float d2 = p[5 + c] - (c == c0 ? 1.0f : 0.0f);
                    acc += d2 * d2;
                }
            } else {
                const float cm = (iou[a] > 0.5f) ? 0.0f : 1.0f;
                const float d  = conf * cm;
                acc = d * d;
            }
        }
    }
    acc *= 0.5f;

    // ================= block reduce + single fire-and-forget RED =================
    acc = warp_sum(acc);
    const int lane = tid & 31, wid = tid >> 5;
    if (lane == 0) s_warp[wid] = acc;
    __syncthreads();
    if (wid == 0) {
        float x = (lane < 16) ? s_warp[lane] : 0.0f;
        x = warp_sum(x);
        if (lane == 0) atomicAdd(loss, x);   // result unused -> RED, no wait
    }
}

extern "C" void kernel_launch(void* const* d_in, const int* in_sizes, int n_in,
                              void* d_out, int out_size) {
    const float* outp = (const float*)d_in[0];
    const float* tgt  = (const float*)d_in[1];
    float* loss = (float*)d_out;
    cudaMemsetAsync(loss, 0, sizeof(float));      // cheap graph memset node
    region_loss_kernel<<<NB, 512>>>(outp, tgt, loss);
}